// round 6
// baseline (speedup 1.0000x reference)
#include <cuda_runtime.h>
#include <cuda_bf16.h>
#include <cstdint>

#define DD 128
#define RR 16
#define NN 50000

// Static device scratch (allocation-free).
__device__ float g_out0[NN * DD];
__device__ float g_out1[NN * DD];
__device__ float g_Z[2 * NN * DD];                 // Z for a relation pair (L2-resident)
__device__ __nv_bfloat16 g_ehi[NN * DD];
__device__ __nv_bfloat16 g_elo[NN * DD];
__device__ __nv_bfloat16 g_Thi[RR * DD * DD];
__device__ __nv_bfloat16 g_Tlo[RR * DD * DD];

static __device__ __forceinline__ uint32_t smem_u32(const void* p) {
    uint32_t a;
    asm("{ .reg .u64 t; cvta.to.shared.u64 t, %1; cvt.u32.u64 %0, t; }" : "=r"(a) : "l"(p));
    return a;
}

static __device__ __forceinline__ void ldsm_x4(uint32_t* r, uint32_t addr) {
    asm volatile("ldmatrix.sync.aligned.m8n8.x4.shared.b16 {%0,%1,%2,%3}, [%4];"
                 : "=r"(r[0]), "=r"(r[1]), "=r"(r[2]), "=r"(r[3]) : "r"(addr));
}

static __device__ __forceinline__ void mma16816(float* d, const uint32_t* a,
                                                uint32_t b0, uint32_t b1) {
    asm volatile(
        "mma.sync.aligned.m16n8k16.row.col.f32.bf16.bf16.f32 "
        "{%0,%1,%2,%3}, {%4,%5,%6,%7}, {%8,%9}, {%0,%1,%2,%3};"
        : "+f"(d[0]), "+f"(d[1]), "+f"(d[2]), "+f"(d[3])
        : "r"(a[0]), "r"(a[1]), "r"(a[2]), "r"(a[3]), "r"(b0), "r"(b1));
}

static __device__ __forceinline__ void cpa16(uint32_t dst, const void* src, bool p) {
    asm volatile("cp.async.ca.shared.global [%0], [%1], 16, %2;"
                 :: "r"(dst), "l"(src), "r"(p ? 16 : 0) : "memory");
}

// smem plane offsets (each 128x128 bf16 = 32 KB, 256B rows, 16B-chunk XOR swizzle)
#define P_AHI 0
#define P_ALO 32768
#define P_B   65536          // 4 planes: r0 hi, r0 lo, r1 hi, r1 lo
#define SMEM_SZ2 (65536 + 4 * 32768)

// ---------------- GEMM: Z[rel][n0..n0+127] = emb @ T_{r0+rel}^T, rel = 0,1 ----------------
// bf16 2-way split: d += Ahi*Bhi + Ahi*Blo + Alo*Bhi, pass-major MMA order so each
// accumulator's RAW reuse distance is 16 MMAs (was 2).
__global__ void __launch_bounds__(256, 1)
gemm2_kernel(const __nv_bfloat16* __restrict__ Ahi, const __nv_bfloat16* __restrict__ Alo,
             const __nv_bfloat16* __restrict__ Thi, const __nv_bfloat16* __restrict__ Tlo,
             float* __restrict__ Z, int r0)
{
    extern __shared__ char sm[];
    const int tid = threadIdx.x;
    const int n0 = blockIdx.x * 128;
    const uint32_t sbase = smem_u32(sm);

    // Group 0: A hi/lo tile + B planes for rel 0 (cp.async, zero-fill OOB rows).
    {
        const uint4* ah = (const uint4*)(Ahi + (size_t)n0 * DD);
        const uint4* al = (const uint4*)(Alo + (size_t)n0 * DD);
        const uint4* b0h = (const uint4*)(Thi + (size_t)r0 * DD * DD);
        const uint4* b0l = (const uint4*)(Tlo + (size_t)r0 * DD * DD);
        #pragma unroll
        for (int i = tid; i < 2048; i += 256) {
            int row = i >> 4, c = i & 15;
            uint32_t off = row * 256 + ((c ^ (row & 7)) << 4);
            bool p = (n0 + row < NN);
            cpa16(sbase + P_AHI + off, ah + i, p);
            cpa16(sbase + P_ALO + off, al + i, p);
            cpa16(sbase + P_B + off, b0h + i, true);
            cpa16(sbase + P_B + 32768 + off, b0l + i, true);
        }
        asm volatile("cp.async.commit_group;" ::: "memory");
    }
    // Group 1: B planes for rel 1 (overlaps with rel-0 compute).
    {
        const uint4* b1h = (const uint4*)(Thi + (size_t)(r0 + 1) * DD * DD);
        const uint4* b1l = (const uint4*)(Tlo + (size_t)(r0 + 1) * DD * DD);
        #pragma unroll
        for (int i = tid; i < 2048; i += 256) {
            int row = i >> 4, c = i & 15;
            uint32_t off = row * 256 + ((c ^ (row & 7)) << 4);
            cpa16(sbase + P_B + 65536 + off, b1h + i, true);
            cpa16(sbase + P_B + 98304 + off, b1l + i, true);
        }
        asm volatile("cp.async.commit_group;" ::: "memory");
    }
    asm volatile("cp.async.wait_group 1;" ::: "memory");
    __syncthreads();

    const int w = tid >> 5, l = tid & 31;
    const int m0w = (w & 3) * 32;        // warp's row offset within tile
    const int n0w = (w >> 2) * 64;       // warp's col offset

    // lane-constant ldmatrix pieces
    const int rA = l & 15;               // A: row-within-16
    const int hiA = l >> 4;              // A: chunk + 0/1
    const int rB = ((l >> 4) << 3) + (l & 7);  // B: row-within-16
    const int hiB = (l >> 3) & 1;        // B: chunk + 0/1

    #pragma unroll 1
    for (int rel = 0; rel < 2; rel++) {
        float d[2][8][4];
        #pragma unroll
        for (int mt = 0; mt < 2; mt++)
            #pragma unroll
            for (int nt = 0; nt < 8; nt++)
                #pragma unroll
                for (int v = 0; v < 4; v++) d[mt][nt][v] = 0.f;

        const uint32_t aHiB = sbase + P_AHI;
        const uint32_t aLoB = sbase + P_ALO;
        const uint32_t bHiB = sbase + P_B + rel * 65536;
        const uint32_t bLoB = bHiB + 32768;

        #pragma unroll
        for (int ks = 0; ks < 8; ks++) {
            uint32_t ah2[2][4], al2[2][4];
            #pragma unroll
            for (int mt = 0; mt < 2; mt++) {
                int rowA = m0w + 16 * mt + rA;
                uint32_t co = ((((ks << 1) + hiA) ^ (rowA & 7)) << 4);
                ldsm_x4(ah2[mt], aHiB + rowA * 256 + co);
                ldsm_x4(al2[mt], aLoB + rowA * 256 + co);
            }
            uint32_t bh[4][4], bl[4][4];
            #pragma unroll
            for (int ntp = 0; ntp < 4; ntp++) {
                int rowB = n0w + 16 * ntp + rB;
                uint32_t co = ((((ks << 1) + hiB) ^ (rowB & 7)) << 4);
                ldsm_x4(bh[ntp], bHiB + rowB * 256 + co);
                ldsm_x4(bl[ntp], bLoB + rowB * 256 + co);
            }
            // pass 0: Ahi * Bhi  (8 d-tiles -> reuse distance 16)
            #pragma unroll
            for (int mt = 0; mt < 2; mt++)
                #pragma unroll
                for (int ntp = 0; ntp < 4; ntp++) {
                    mma16816(d[mt][2 * ntp],     ah2[mt], bh[ntp][0], bh[ntp][1]);
                    mma16816(d[mt][2 * ntp + 1], ah2[mt], bh[ntp][2], bh[ntp][3]);
                }
            // pass 1: Ahi * Blo
            #pragma unroll
            for (int mt = 0; mt < 2; mt++)
                #pragma unroll
                for (int ntp = 0; ntp < 4; ntp++) {
                    mma16816(d[mt][2 * ntp],     ah2[mt], bl[ntp][0], bl[ntp][1]);
                    mma16816(d[mt][2 * ntp + 1], ah2[mt], bl[ntp][2], bl[ntp][3]);
                }
            // pass 2: Alo * Bhi
            #pragma unroll
            for (int mt = 0; mt < 2; mt++)
                #pragma unroll
                for (int ntp = 0; ntp < 4; ntp++) {
                    mma16816(d[mt][2 * ntp],     al2[mt], bh[ntp][0], bh[ntp][1]);
                    mma16816(d[mt][2 * ntp + 1], al2[mt], bh[ntp][2], bh[ntp][3]);
                }
        }

        // Epilogue: C frag (c0,c1)->(row, col..col+1), (c2,c3)->(row+8, ...)
        #pragma unroll
        for (int mt = 0; mt < 2; mt++) {
            int row = n0 + m0w + 16 * mt + (l >> 2);
            float* zp0 = Z + ((size_t)rel * NN + row) * DD;
            float* zp1 = zp0 + 8 * DD;
            if (row < NN) {
                #pragma unroll
                for (int nt = 0; nt < 8; nt++) {
                    int col = n0w + 8 * nt + 2 * (l & 3);
                    *(float2*)(zp0 + col) = make_float2(d[mt][nt][0], d[mt][nt][1]);
                }
            }
            if (row + 8 < NN) {
                #pragma unroll
                for (int nt = 0; nt < 8; nt++) {
                    int col = n0w + 8 * nt + 2 * (l & 3);
                    *(float2*)(zp1 + col) = make_float2(d[mt][nt][2], d[mt][nt][3]);
                }
            }
        }

        if (rel == 0) {
            asm volatile("cp.async.wait_group 0;" ::: "memory");
            __syncthreads();
        }
    }
}

// ---------------- scatter: out[row] += val * Z[rr][col]  (1 warp per edge) ----------------
__global__ void __launch_bounds__(256, 4)
scatter_kernel(const float* __restrict__ Z, const float* __restrict__ ev,
               const int* __restrict__ er, const int* __restrict__ ec,
               float* __restrict__ out, int E, int r0)
{
    int ge = blockIdx.x * 8 + (threadIdx.x >> 5);
    if (ge >= 2 * E) return;
    int lane = threadIdx.x & 31;
    int rr = ge / E;
    int e = ge - rr * E;
    int r = r0 + rr;
    int col = __ldg(ec + r * E + e);
    int row = __ldg(er + r * E + e);
    float val = __ldg(ev + r * E + e);
    float4 v = *(const float4*)(Z + ((size_t)rr * NN + col) * DD + lane * 4);
    v.x *= val; v.y *= val; v.z *= val; v.w *= val;
    float* dst = out + (size_t)row * DD + lane * 4;
    asm volatile("red.global.add.v4.f32 [%0], {%1,%2,%3,%4};"
                 :: "l"(dst), "f"(v.x), "f"(v.y), "f"(v.z), "f"(v.w) : "memory");
}

// ---------------- split fp32 -> bf16 hi/lo, 8 elems/thread (optionally relu) ----------------
__global__ void split_kernel(const float* __restrict__ in, __nv_bfloat16* __restrict__ hi,
                             __nv_bfloat16* __restrict__ lo, int n8, int doRelu)
{
    int i = blockIdx.x * 256 + threadIdx.x;
    if (i >= n8) return;
    const float4* in4 = (const float4*)in + 2 * (size_t)i;
    float4 x0 = in4[0], x1 = in4[1];
    float xs[8] = {x0.x, x0.y, x0.z, x0.w, x1.x, x1.y, x1.z, x1.w};
    __nv_bfloat16 hs[8], ls[8];
    #pragma unroll
    for (int k = 0; k < 8; k++) {
        float x = xs[k];
        if (doRelu) x = fmaxf(x, 0.f);
        __nv_bfloat16 h = __float2bfloat16(x);
        hs[k] = h;
        ls[k] = __float2bfloat16(x - __bfloat162float(h));
    }
    *((uint4*)hi + i) = *(uint4*)hs;
    *((uint4*)lo + i) = *(uint4*)ls;
}

__global__ void zero4_kernel(float4* __restrict__ p, int n) {
    int i = blockIdx.x * 256 + threadIdx.x;
    if (i < n) p[i] = make_float4(0.f, 0.f, 0.f, 0.f);
}

// Final: relu + L2 row-normalize. One warp per row.
__global__ void norm_kernel(const float* __restrict__ in, float* __restrict__ out, int n) {
    int row = blockIdx.x * 8 + (threadIdx.x >> 5);
    int lane = threadIdx.x & 31;
    if (row >= n) return;
    float4 v = *reinterpret_cast<const float4*>(in + (size_t)row * DD + lane * 4);
    v.x = fmaxf(v.x, 0.f); v.y = fmaxf(v.y, 0.f);
    v.z = fmaxf(v.z, 0.f); v.w = fmaxf(v.w, 0.f);
    float s = v.x * v.x + v.y * v.y + v.z * v.z + v.w * v.w;
    #pragma unroll
    for (int o = 16; o; o >>= 1) s += __shfl_xor_sync(0xffffffffu, s, o);
    float sc = 1.f / fmaxf(sqrtf(s), 1e-12f);
    v.x *= sc; v.y *= sc; v.z *= sc; v.w *= sc;
    *reinterpret_cast<float4*>(out + (size_t)row * DD + lane * 4) = v;
}

extern "C" void kernel_launch(void* const* d_in, const int* in_sizes, int n_in,
                              void* d_out, int out_size) {
    const float* ent = (const float*)d_in[0];   // [N, D]
    const float* Tm  = (const float*)d_in[1];   // [R, D, D]
    const float* ev  = (const float*)d_in[2];   // [R, E]
    const int*   er  = (const int*)d_in[3];     // [R, E]
    const int*   ec  = (const int*)d_in[4];     // [R, E]
    float* out = (float*)d_out;

    const int E = in_sizes[2] / RR;

    float *out0, *out1, *Z;
    __nv_bfloat16 *ehi, *elo, *Thi, *Tlo;
    cudaGetSymbolAddress((void**)&out0, g_out0);
    cudaGetSymbolAddress((void**)&out1, g_out1);
    cudaGetSymbolAddress((void**)&Z, g_Z);
    cudaGetSymbolAddress((void**)&ehi, g_ehi);
    cudaGetSymbolAddress((void**)&elo, g_elo);
    cudaGetSymbolAddress((void**)&Thi, g_Thi);
    cudaGetSymbolAddress((void**)&Tlo, g_Tlo);

    cudaFuncSetAttribute(gemm2_kernel, cudaFuncAttributeMaxDynamicSharedMemorySize, SMEM_SZ2);

    const int nE = NN * DD;                 // 6.4M
    const int nT = RR * DD * DD;
    const int rowTiles = (NN + 127) / 128;  // 391
    const int sgrid = (2 * E + 7) / 8;

    // Split relation matrices.
    split_kernel<<<(nT / 8 + 255) / 256, 256>>>(Tm, Thi, Tlo, nT / 8, 0);

    // ---- layer 1 ----
    split_kernel<<<(nE / 8 + 255) / 256, 256>>>(ent, ehi, elo, nE / 8, 0);
    zero4_kernel<<<(nE / 4 + 255) / 256, 256>>>((float4*)out0, nE / 4);
    for (int r0 = 0; r0 < RR; r0 += 2) {
        gemm2_kernel<<<rowTiles, 256, SMEM_SZ2>>>(ehi, elo, Thi, Tlo, Z, r0);
        scatter_kernel<<<sgrid, 256>>>(Z, ev, er, ec, out0, E, r0);
    }

    // ---- layer 2 ----
    split_kernel<<<(nE / 8 + 255) / 256, 256>>>(out0, ehi, elo, nE / 8, 1);
    zero4_kernel<<<(nE / 4 + 255) / 256, 256>>>((float4*)out1, nE / 4);
    for (int r0 = 0; r0 < RR; r0 += 2) {
        gemm2_kernel<<<rowTiles, 256, SMEM_SZ2>>>(ehi, elo, Thi, Tlo, Z, r0);
        scatter_kernel<<<sgrid, 256>>>(Z, ev, er, ec, out1, E, r0);
    }

    norm_kernel<<<(NN + 7) / 8, 256>>>(out1, out, NN);
}

// round 7
// speedup vs baseline: 1.0217x; 1.0217x over previous
#include <cuda_runtime.h>
#include <cuda_bf16.h>
#include <cstdint>

#define DD 128
#define RR 16
#define NN 50000

// Static device scratch (allocation-free).
__device__ float g_out0[NN * DD];
__device__ float g_out1[NN * DD];
__device__ float g_Z[4 * NN * DD];                 // 2 pair-buffers (double-buffered)
__device__ __nv_bfloat16 g_ehi[NN * DD];
__device__ __nv_bfloat16 g_elo[NN * DD];
__device__ __nv_bfloat16 g_Thi[RR * DD * DD];
__device__ __nv_bfloat16 g_Tlo[RR * DD * DD];

static __device__ __forceinline__ uint32_t smem_u32(const void* p) {
    uint32_t a;
    asm("{ .reg .u64 t; cvta.to.shared.u64 t, %1; cvt.u32.u64 %0, t; }" : "=r"(a) : "l"(p));
    return a;
}

static __device__ __forceinline__ void ldsm_x4(uint32_t* r, uint32_t addr) {
    asm volatile("ldmatrix.sync.aligned.m8n8.x4.shared.b16 {%0,%1,%2,%3}, [%4];"
                 : "=r"(r[0]), "=r"(r[1]), "=r"(r[2]), "=r"(r[3]) : "r"(addr));
}

static __device__ __forceinline__ void mma16816(float* d, const uint32_t* a,
                                                uint32_t b0, uint32_t b1) {
    asm volatile(
        "mma.sync.aligned.m16n8k16.row.col.f32.bf16.bf16.f32 "
        "{%0,%1,%2,%3}, {%4,%5,%6,%7}, {%8,%9}, {%0,%1,%2,%3};"
        : "+f"(d[0]), "+f"(d[1]), "+f"(d[2]), "+f"(d[3])
        : "r"(a[0]), "r"(a[1]), "r"(a[2]), "r"(a[3]), "r"(b0), "r"(b1));
}

static __device__ __forceinline__ void cpa16(uint32_t dst, const void* src, bool p) {
    asm volatile("cp.async.ca.shared.global [%0], [%1], 16, %2;"
                 :: "r"(dst), "l"(src), "r"(p ? 16 : 0) : "memory");
}

// smem plane offsets (each 128x128 bf16 = 32 KB, 256B rows, 16B-chunk XOR swizzle)
#define P_AHI 0
#define P_ALO 32768
#define P_B   65536          // 4 planes: r0 hi, r0 lo, r1 hi, r1 lo
#define SMEM_SZ2 (65536 + 4 * 32768)

// ---------------- GEMM: Z[rel][n0..n0+127] = emb @ T_{r0+rel}^T, rel = 0,1 ----------------
// bf16 2-way split: d += Ahi*Bhi + Ahi*Blo + Alo*Bhi. Near legacy-HMMA pipe floor.
__global__ void __launch_bounds__(256, 1)
gemm2_kernel(const __nv_bfloat16* __restrict__ Ahi, const __nv_bfloat16* __restrict__ Alo,
             const __nv_bfloat16* __restrict__ Thi, const __nv_bfloat16* __restrict__ Tlo,
             float* __restrict__ Z, int r0)
{
    extern __shared__ char sm[];
    const int tid = threadIdx.x;
    const int n0 = blockIdx.x * 128;
    const uint32_t sbase = smem_u32(sm);

    // Group 0: A hi/lo tile + B planes for rel 0 (cp.async, zero-fill OOB rows).
    {
        const uint4* ah = (const uint4*)(Ahi + (size_t)n0 * DD);
        const uint4* al = (const uint4*)(Alo + (size_t)n0 * DD);
        const uint4* b0h = (const uint4*)(Thi + (size_t)r0 * DD * DD);
        const uint4* b0l = (const uint4*)(Tlo + (size_t)r0 * DD * DD);
        #pragma unroll
        for (int i = tid; i < 2048; i += 256) {
            int row = i >> 4, c = i & 15;
            uint32_t off = row * 256 + ((c ^ (row & 7)) << 4);
            bool p = (n0 + row < NN);
            cpa16(sbase + P_AHI + off, ah + i, p);
            cpa16(sbase + P_ALO + off, al + i, p);
            cpa16(sbase + P_B + off, b0h + i, true);
            cpa16(sbase + P_B + 32768 + off, b0l + i, true);
        }
        asm volatile("cp.async.commit_group;" ::: "memory");
    }
    // Group 1: B planes for rel 1 (overlaps with rel-0 compute).
    {
        const uint4* b1h = (const uint4*)(Thi + (size_t)(r0 + 1) * DD * DD);
        const uint4* b1l = (const uint4*)(Tlo + (size_t)(r0 + 1) * DD * DD);
        #pragma unroll
        for (int i = tid; i < 2048; i += 256) {
            int row = i >> 4, c = i & 15;
            uint32_t off = row * 256 + ((c ^ (row & 7)) << 4);
            cpa16(sbase + P_B + 65536 + off, b1h + i, true);
            cpa16(sbase + P_B + 98304 + off, b1l + i, true);
        }
        asm volatile("cp.async.commit_group;" ::: "memory");
    }
    asm volatile("cp.async.wait_group 1;" ::: "memory");
    __syncthreads();

    const int w = tid >> 5, l = tid & 31;
    const int m0w = (w & 3) * 32;        // warp's row offset within tile
    const int n0w = (w >> 2) * 64;       // warp's col offset

    // lane-constant ldmatrix pieces
    const int rA = l & 15;               // A: row-within-16
    const int hiA = l >> 4;              // A: chunk + 0/1
    const int rB = ((l >> 4) << 3) + (l & 7);  // B: row-within-16
    const int hiB = (l >> 3) & 1;        // B: chunk + 0/1

    #pragma unroll 1
    for (int rel = 0; rel < 2; rel++) {
        float d[2][8][4];
        #pragma unroll
        for (int mt = 0; mt < 2; mt++)
            #pragma unroll
            for (int nt = 0; nt < 8; nt++)
                #pragma unroll
                for (int v = 0; v < 4; v++) d[mt][nt][v] = 0.f;

        const uint32_t aHiB = sbase + P_AHI;
        const uint32_t aLoB = sbase + P_ALO;
        const uint32_t bHiB = sbase + P_B + rel * 65536;
        const uint32_t bLoB = bHiB + 32768;

        #pragma unroll
        for (int ks = 0; ks < 8; ks++) {
            uint32_t ah2[2][4], al2[2][4];
            #pragma unroll
            for (int mt = 0; mt < 2; mt++) {
                int rowA = m0w + 16 * mt + rA;
                uint32_t co = ((((ks << 1) + hiA) ^ (rowA & 7)) << 4);
                ldsm_x4(ah2[mt], aHiB + rowA * 256 + co);
                ldsm_x4(al2[mt], aLoB + rowA * 256 + co);
            }
            uint32_t bh[4][4], bl[4][4];
            #pragma unroll
            for (int ntp = 0; ntp < 4; ntp++) {
                int rowB = n0w + 16 * ntp + rB;
                uint32_t co = ((((ks << 1) + hiB) ^ (rowB & 7)) << 4);
                ldsm_x4(bh[ntp], bHiB + rowB * 256 + co);
                ldsm_x4(bl[ntp], bLoB + rowB * 256 + co);
            }
            #pragma unroll
            for (int mt = 0; mt < 2; mt++)
                #pragma unroll
                for (int ntp = 0; ntp < 4; ntp++) {
                    mma16816(d[mt][2 * ntp],     ah2[mt], bh[ntp][0], bh[ntp][1]);
                    mma16816(d[mt][2 * ntp + 1], ah2[mt], bh[ntp][2], bh[ntp][3]);
                    mma16816(d[mt][2 * ntp],     ah2[mt], bl[ntp][0], bl[ntp][1]);
                    mma16816(d[mt][2 * ntp + 1], ah2[mt], bl[ntp][2], bl[ntp][3]);
                    mma16816(d[mt][2 * ntp],     al2[mt], bh[ntp][0], bh[ntp][1]);
                    mma16816(d[mt][2 * ntp + 1], al2[mt], bh[ntp][2], bh[ntp][3]);
                }
        }

        // Epilogue: C frag (c0,c1)->(row, col..col+1), (c2,c3)->(row+8, ...)
        #pragma unroll
        for (int mt = 0; mt < 2; mt++) {
            int row = n0 + m0w + 16 * mt + (l >> 2);
            float* zp0 = Z + ((size_t)rel * NN + row) * DD;
            float* zp1 = zp0 + 8 * DD;
            if (row < NN) {
                #pragma unroll
                for (int nt = 0; nt < 8; nt++) {
                    int col = n0w + 8 * nt + 2 * (l & 3);
                    *(float2*)(zp0 + col) = make_float2(d[mt][nt][0], d[mt][nt][1]);
                }
            }
            if (row + 8 < NN) {
                #pragma unroll
                for (int nt = 0; nt < 8; nt++) {
                    int col = n0w + 8 * nt + 2 * (l & 3);
                    *(float2*)(zp1 + col) = make_float2(d[mt][nt][2], d[mt][nt][3]);
                }
            }
        }

        if (rel == 0) {
            asm volatile("cp.async.wait_group 0;" ::: "memory");
            __syncthreads();
        }
    }
}

// ---------------- scatter: out[row] += val * Z[rr][col]  (1 warp per edge) ----------------
__global__ void __launch_bounds__(256, 4)
scatter_kernel(const float* __restrict__ Z, const float* __restrict__ ev,
               const int* __restrict__ er, const int* __restrict__ ec,
               float* __restrict__ out, int E, int r0)
{
    int ge = blockIdx.x * 8 + (threadIdx.x >> 5);
    if (ge >= 2 * E) return;
    int lane = threadIdx.x & 31;
    int rr = ge / E;
    int e = ge - rr * E;
    int r = r0 + rr;
    int col = __ldg(ec + r * E + e);
    int row = __ldg(er + r * E + e);
    float val = __ldg(ev + r * E + e);
    float4 v = *(const float4*)(Z + ((size_t)rr * NN + col) * DD + lane * 4);
    v.x *= val; v.y *= val; v.z *= val; v.w *= val;
    float* dst = out + (size_t)row * DD + lane * 4;
    asm volatile("red.global.add.v4.f32 [%0], {%1,%2,%3,%4};"
                 :: "l"(dst), "f"(v.x), "f"(v.y), "f"(v.z), "f"(v.w) : "memory");
}

// ---------------- split fp32 -> bf16 hi/lo, 8 elems/thread (optionally relu) ----------------
__global__ void split_kernel(const float* __restrict__ in, __nv_bfloat16* __restrict__ hi,
                             __nv_bfloat16* __restrict__ lo, int n8, int doRelu)
{
    int i = blockIdx.x * 256 + threadIdx.x;
    if (i >= n8) return;
    const float4* in4 = (const float4*)in + 2 * (size_t)i;
    float4 x0 = in4[0], x1 = in4[1];
    float xs[8] = {x0.x, x0.y, x0.z, x0.w, x1.x, x1.y, x1.z, x1.w};
    __nv_bfloat16 hs[8], ls[8];
    #pragma unroll
    for (int k = 0; k < 8; k++) {
        float x = xs[k];
        if (doRelu) x = fmaxf(x, 0.f);
        __nv_bfloat16 h = __float2bfloat16(x);
        hs[k] = h;
        ls[k] = __float2bfloat16(x - __bfloat162float(h));
    }
    *((uint4*)hi + i) = *(uint4*)hs;
    *((uint4*)lo + i) = *(uint4*)ls;
}

__global__ void zero4_kernel(float4* __restrict__ p, int n) {
    int i = blockIdx.x * 256 + threadIdx.x;
    if (i < n) p[i] = make_float4(0.f, 0.f, 0.f, 0.f);
}

// Final: relu + L2 row-normalize. One warp per row.
__global__ void norm_kernel(const float* __restrict__ in, float* __restrict__ out, int n) {
    int row = blockIdx.x * 8 + (threadIdx.x >> 5);
    int lane = threadIdx.x & 31;
    if (row >= n) return;
    float4 v = *reinterpret_cast<const float4*>(in + (size_t)row * DD + lane * 4);
    v.x = fmaxf(v.x, 0.f); v.y = fmaxf(v.y, 0.f);
    v.z = fmaxf(v.z, 0.f); v.w = fmaxf(v.w, 0.f);
    float s = v.x * v.x + v.y * v.y + v.z * v.z + v.w * v.w;
    #pragma unroll
    for (int o = 16; o; o >>= 1) s += __shfl_xor_sync(0xffffffffu, s, o);
    float sc = 1.f / fmaxf(sqrtf(s), 1e-12f);
    v.x *= sc; v.y *= sc; v.z *= sc; v.w *= sc;
    *reinterpret_cast<float4*>(out + (size_t)row * DD + lane * 4) = v;
}

extern "C" void kernel_launch(void* const* d_in, const int* in_sizes, int n_in,
                              void* d_out, int out_size) {
    const float* ent = (const float*)d_in[0];   // [N, D]
    const float* Tm  = (const float*)d_in[1];   // [R, D, D]
    const float* ev  = (const float*)d_in[2];   // [R, E]
    const int*   er  = (const int*)d_in[3];     // [R, E]
    const int*   ec  = (const int*)d_in[4];     // [R, E]
    float* out = (float*)d_out;

    const int E = in_sizes[2] / RR;

    float *out0, *out1, *Z;
    __nv_bfloat16 *ehi, *elo, *Thi, *Tlo;
    cudaGetSymbolAddress((void**)&out0, g_out0);
    cudaGetSymbolAddress((void**)&out1, g_out1);
    cudaGetSymbolAddress((void**)&Z, g_Z);
    cudaGetSymbolAddress((void**)&ehi, g_ehi);
    cudaGetSymbolAddress((void**)&elo, g_elo);
    cudaGetSymbolAddress((void**)&Thi, g_Thi);
    cudaGetSymbolAddress((void**)&Tlo, g_Tlo);

    cudaFuncSetAttribute(gemm2_kernel, cudaFuncAttributeMaxDynamicSharedMemorySize, SMEM_SZ2);

    const int nE = NN * DD;                 // 6.4M
    const int nT = RR * DD * DD;
    const int rowTiles = (NN + 127) / 128;  // 391
    const int sgrid = (2 * E + 7) / 8;
    const size_t ZPAIR = 2 * (size_t)NN * DD;   // one pair-buffer

    // Fork-join capture: scatters run on a side stream, hidden under the next gemm.
    // Host objects created per call (graph retains topology; no device allocation).
    cudaStream_t s1;
    cudaStreamCreateWithFlags(&s1, cudaStreamNonBlocking);
    cudaEvent_t evFork, evG[16], evS[16], evJoin[2];
    cudaEventCreateWithFlags(&evFork, cudaEventDisableTiming);
    cudaEventCreateWithFlags(&evJoin[0], cudaEventDisableTiming);
    cudaEventCreateWithFlags(&evJoin[1], cudaEventDisableTiming);
    for (int i = 0; i < 16; i++) {
        cudaEventCreateWithFlags(&evG[i], cudaEventDisableTiming);
        cudaEventCreateWithFlags(&evS[i], cudaEventDisableTiming);
    }

    // Fork side stream; zero out1 early on it (untouched until layer 2).
    cudaEventRecord(evFork, 0);
    cudaStreamWaitEvent(s1, evFork, 0);
    zero4_kernel<<<(nE / 4 + 255) / 256, 256, 0, s1>>>((float4*)out1, nE / 4);

    // Main stream: splits + zero(out0).
    split_kernel<<<(nT / 8 + 255) / 256, 256>>>(Tm, Thi, Tlo, nT / 8, 0);
    split_kernel<<<(nE / 8 + 255) / 256, 256>>>(ent, ehi, elo, nE / 8, 0);
    zero4_kernel<<<(nE / 4 + 255) / 256, 256>>>((float4*)out0, nE / 4);

    // ---- layer 1: gemm chain on main stream, scatters on s1 ----
    for (int p = 0; p < 8; p++) {
        float* Zb = Z + (p & 1) * ZPAIR;
        if (p >= 2) cudaStreamWaitEvent(0, evS[p - 2], 0);  // buffer reuse guard
        gemm2_kernel<<<rowTiles, 256, SMEM_SZ2>>>(ehi, elo, Thi, Tlo, Zb, 2 * p);
        cudaEventRecord(evG[p], 0);
        cudaStreamWaitEvent(s1, evG[p], 0);
        scatter_kernel<<<sgrid, 256, 0, s1>>>(Zb, ev, er, ec, out0, E, 2 * p);
        cudaEventRecord(evS[p], s1);
    }
    cudaEventRecord(evJoin[0], s1);
    cudaStreamWaitEvent(0, evS[7], 0);

    // ---- layer 2 ----
    split_kernel<<<(nE / 8 + 255) / 256, 256>>>(out0, ehi, elo, nE / 8, 1);
    cudaStreamWaitEvent(0, evJoin[0], 0);   // ensure zero(out1) done (s1 in-order anyway)
    for (int p = 0; p < 8; p++) {
        float* Zb = Z + (p & 1) * ZPAIR;
        if (p >= 2) cudaStreamWaitEvent(0, evS[8 + p - 2], 0);
        gemm2_kernel<<<rowTiles, 256, SMEM_SZ2>>>(ehi, elo, Thi, Tlo, Zb, 2 * p);
        cudaEventRecord(evG[8 + p], 0);
        cudaStreamWaitEvent(s1, evG[8 + p], 0);
        scatter_kernel<<<sgrid, 256, 0, s1>>>(Zb, ev, er, ec, out1, E, 2 * p);
        cudaEventRecord(evS[8 + p], s1);
    }
    cudaStreamWaitEvent(0, evS[15], 0);

    norm_kernel<<<(NN + 7) / 8, 256>>>(out1, out, NN);

    // Intentionally not destroying events/stream while capture may be active;
    // host-object leak per call is bounded (kernel_launch runs O(1) times).
}

// round 9
// speedup vs baseline: 1.0971x; 1.0738x over previous
#include <cuda_runtime.h>
#include <cuda_bf16.h>
#include <cstdint>

#define DD 128
#define RR 16
#define NN 50000

// Static device scratch (allocation-free).
__device__ float g_out0[NN * DD];
__device__ float g_out1[NN * DD];
__device__ float g_Z[8 * NN * DD];                 // 4 pair-buffers
__device__ __nv_bfloat16 g_ehi[NN * DD];
__device__ __nv_bfloat16 g_elo[NN * DD];
__device__ __nv_bfloat16 g_Thi[RR * DD * DD];
__device__ __nv_bfloat16 g_Tlo[RR * DD * DD];

static __device__ __forceinline__ uint32_t smem_u32(const void* p) {
    uint32_t a;
    asm("{ .reg .u64 t; cvta.to.shared.u64 t, %1; cvt.u32.u64 %0, t; }" : "=r"(a) : "l"(p));
    return a;
}

static __device__ __forceinline__ void ldsm_x4(uint32_t* r, uint32_t addr) {
    asm volatile("ldmatrix.sync.aligned.m8n8.x4.shared.b16 {%0,%1,%2,%3}, [%4];"
                 : "=r"(r[0]), "=r"(r[1]), "=r"(r[2]), "=r"(r[3]) : "r"(addr));
}

static __device__ __forceinline__ void mma16816(float* d, const uint32_t* a,
                                                uint32_t b0, uint32_t b1) {
    asm volatile(
        "mma.sync.aligned.m16n8k16.row.col.f32.bf16.bf16.f32 "
        "{%0,%1,%2,%3}, {%4,%5,%6,%7}, {%8,%9}, {%0,%1,%2,%3};"
        : "+f"(d[0]), "+f"(d[1]), "+f"(d[2]), "+f"(d[3])
        : "r"(a[0]), "r"(a[1]), "r"(a[2]), "r"(a[3]), "r"(b0), "r"(b1));
}

static __device__ __forceinline__ void cpa16(uint32_t dst, const void* src, bool p) {
    asm volatile("cp.async.ca.shared.global [%0], [%1], 16, %2;"
                 :: "r"(dst), "l"(src), "r"(p ? 16 : 0) : "memory");
}

// smem plane offsets (each 128x128 bf16 = 32 KB, 256B rows, 16B-chunk XOR swizzle)
#define P_AHI 0
#define P_ALO 32768
#define P_B   65536          // 4 planes: r0 hi, r0 lo, r1 hi, r1 lo
#define SMEM_SZ2 (65536 + 4 * 32768)

// ---------------- GEMM: Z[rel][n0..n0+127] = emb @ T_{r0+rel}^T, rel = 0,1 ----------------
// bf16 2-way split: d += Ahi*Bhi + Ahi*Blo + Alo*Bhi. At the legacy-HMMA pipe floor.
__global__ void __launch_bounds__(256, 1)
gemm2_kernel(const __nv_bfloat16* __restrict__ Ahi, const __nv_bfloat16* __restrict__ Alo,
             const __nv_bfloat16* __restrict__ Thi, const __nv_bfloat16* __restrict__ Tlo,
             float* __restrict__ Z, int r0)
{
    extern __shared__ char sm[];
    const int tid = threadIdx.x;
    const int n0 = blockIdx.x * 128;
    const uint32_t sbase = smem_u32(sm);

    // Group 0: A hi/lo tile + B planes for rel 0 (cp.async, zero-fill OOB rows).
    {
        const uint4* ah = (const uint4*)(Ahi + (size_t)n0 * DD);
        const uint4* al = (const uint4*)(Alo + (size_t)n0 * DD);
        const uint4* b0h = (const uint4*)(Thi + (size_t)r0 * DD * DD);
        const uint4* b0l = (const uint4*)(Tlo + (size_t)r0 * DD * DD);
        #pragma unroll
        for (int i = tid; i < 2048; i += 256) {
            int row = i >> 4, c = i & 15;
            uint32_t off = row * 256 + ((c ^ (row & 7)) << 4);
            bool p = (n0 + row < NN);
            cpa16(sbase + P_AHI + off, ah + i, p);
            cpa16(sbase + P_ALO + off, al + i, p);
            cpa16(sbase + P_B + off, b0h + i, true);
            cpa16(sbase + P_B + 32768 + off, b0l + i, true);
        }
        asm volatile("cp.async.commit_group;" ::: "memory");
    }
    // Group 1: B planes for rel 1 (overlaps with rel-0 compute).
    {
        const uint4* b1h = (const uint4*)(Thi + (size_t)(r0 + 1) * DD * DD);
        const uint4* b1l = (const uint4*)(Tlo + (size_t)(r0 + 1) * DD * DD);
        #pragma unroll
        for (int i = tid; i < 2048; i += 256) {
            int row = i >> 4, c = i & 15;
            uint32_t off = row * 256 + ((c ^ (row & 7)) << 4);
            cpa16(sbase + P_B + 65536 + off, b1h + i, true);
            cpa16(sbase + P_B + 98304 + off, b1l + i, true);
        }
        asm volatile("cp.async.commit_group;" ::: "memory");
    }
    asm volatile("cp.async.wait_group 1;" ::: "memory");
    __syncthreads();

    const int w = tid >> 5, l = tid & 31;
    const int m0w = (w & 3) * 32;        // warp's row offset within tile
    const int n0w = (w >> 2) * 64;       // warp's col offset

    // lane-constant ldmatrix pieces
    const int rA = l & 15;               // A: row-within-16
    const int hiA = l >> 4;              // A: chunk + 0/1
    const int rB = ((l >> 4) << 3) + (l & 7);  // B: row-within-16
    const int hiB = (l >> 3) & 1;        // B: chunk + 0/1

    #pragma unroll 1
    for (int rel = 0; rel < 2; rel++) {
        float d[2][8][4];
        #pragma unroll
        for (int mt = 0; mt < 2; mt++)
            #pragma unroll
            for (int nt = 0; nt < 8; nt++)
                #pragma unroll
                for (int v = 0; v < 4; v++) d[mt][nt][v] = 0.f;

        const uint32_t aHiB = sbase + P_AHI;
        const uint32_t aLoB = sbase + P_ALO;
        const uint32_t bHiB = sbase + P_B + rel * 65536;
        const uint32_t bLoB = bHiB + 32768;

        #pragma unroll
        for (int ks = 0; ks < 8; ks++) {
            uint32_t ah2[2][4], al2[2][4];
            #pragma unroll
            for (int mt = 0; mt < 2; mt++) {
                int rowA = m0w + 16 * mt + rA;
                uint32_t co = ((((ks << 1) + hiA) ^ (rowA & 7)) << 4);
                ldsm_x4(ah2[mt], aHiB + rowA * 256 + co);
                ldsm_x4(al2[mt], aLoB + rowA * 256 + co);
            }
            uint32_t bh[4][4], bl[4][4];
            #pragma unroll
            for (int ntp = 0; ntp < 4; ntp++) {
                int rowB = n0w + 16 * ntp + rB;
                uint32_t co = ((((ks << 1) + hiB) ^ (rowB & 7)) << 4);
                ldsm_x4(bh[ntp], bHiB + rowB * 256 + co);
                ldsm_x4(bl[ntp], bLoB + rowB * 256 + co);
            }
            #pragma unroll
            for (int mt = 0; mt < 2; mt++)
                #pragma unroll
                for (int ntp = 0; ntp < 4; ntp++) {
                    mma16816(d[mt][2 * ntp],     ah2[mt], bh[ntp][0], bh[ntp][1]);
                    mma16816(d[mt][2 * ntp + 1], ah2[mt], bh[ntp][2], bh[ntp][3]);
                    mma16816(d[mt][2 * ntp],     ah2[mt], bl[ntp][0], bl[ntp][1]);
                    mma16816(d[mt][2 * ntp + 1], ah2[mt], bl[ntp][2], bl[ntp][3]);
                    mma16816(d[mt][2 * ntp],     al2[mt], bh[ntp][0], bh[ntp][1]);
                    mma16816(d[mt][2 * ntp + 1], al2[mt], bh[ntp][2], bh[ntp][3]);
                }
        }

        // Epilogue: C frag (c0,c1)->(row, col..col+1), (c2,c3)->(row+8, ...)
        #pragma unroll
        for (int mt = 0; mt < 2; mt++) {
            int row = n0 + m0w + 16 * mt + (l >> 2);
            float* zp0 = Z + ((size_t)rel * NN + row) * DD;
            float* zp1 = zp0 + 8 * DD;
            if (row < NN) {
                #pragma unroll
                for (int nt = 0; nt < 8; nt++) {
                    int col = n0w + 8 * nt + 2 * (l & 3);
                    *(float2*)(zp0 + col) = make_float2(d[mt][nt][0], d[mt][nt][1]);
                }
            }
            if (row + 8 < NN) {
                #pragma unroll
                for (int nt = 0; nt < 8; nt++) {
                    int col = n0w + 8 * nt + 2 * (l & 3);
                    *(float2*)(zp1 + col) = make_float2(d[mt][nt][2], d[mt][nt][3]);
                }
            }
        }

        if (rel == 0) {
            asm volatile("cp.async.wait_group 0;" ::: "memory");
            __syncthreads();
        }
    }
}

// ---------------- scatter: out[row] += val * Z[rr][col]  (1 warp per edge) ----------------
__global__ void __launch_bounds__(256, 4)
scatter_kernel(const float* __restrict__ Z, const float* __restrict__ ev,
               const int* __restrict__ er, const int* __restrict__ ec,
               float* __restrict__ out, int E, int r0)
{
    int ge = blockIdx.x * 8 + (threadIdx.x >> 5);
    if (ge >= 2 * E) return;
    int lane = threadIdx.x & 31;
    int rr = ge / E;
    int e = ge - rr * E;
    int r = r0 + rr;
    int col = __ldg(ec + r * E + e);
    int row = __ldg(er + r * E + e);
    float val = __ldg(ev + r * E + e);
    float4 v = *(const float4*)(Z + ((size_t)rr * NN + col) * DD + lane * 4);
    v.x *= val; v.y *= val; v.z *= val; v.w *= val;
    float* dst = out + (size_t)row * DD + lane * 4;
    asm volatile("red.global.add.v4.f32 [%0], {%1,%2,%3,%4};"
                 :: "l"(dst), "f"(v.x), "f"(v.y), "f"(v.z), "f"(v.w) : "memory");
}

// ---------------- split fp32 -> bf16 hi/lo, 8 elems/thread (optionally relu) ----------------
__global__ void split_kernel(const float* __restrict__ in, __nv_bfloat16* __restrict__ hi,
                             __nv_bfloat16* __restrict__ lo, int n8, int doRelu)
{
    int i = blockIdx.x * 256 + threadIdx.x;
    if (i >= n8) return;
    const float4* in4 = (const float4*)in + 2 * (size_t)i;
    float4 x0 = in4[0], x1 = in4[1];
    float xs[8] = {x0.x, x0.y, x0.z, x0.w, x1.x, x1.y, x1.z, x1.w};
    __nv_bfloat16 hs[8], ls[8];
    #pragma unroll
    for (int k = 0; k < 8; k++) {
        float x = xs[k];
        if (doRelu) x = fmaxf(x, 0.f);
        __nv_bfloat16 h = __float2bfloat16(x);
        hs[k] = h;
        ls[k] = __float2bfloat16(x - __bfloat162float(h));
    }
    *((uint4*)hi + i) = *(uint4*)hs;
    *((uint4*)lo + i) = *(uint4*)ls;
}

__global__ void zero4_kernel(float4* __restrict__ p, int n) {
    int i = blockIdx.x * 256 + threadIdx.x;
    if (i < n) p[i] = make_float4(0.f, 0.f, 0.f, 0.f);
}

// Final: relu + L2 row-normalize. One warp per row.
__global__ void norm_kernel(const float* __restrict__ in, float* __restrict__ out, int n) {
    int row = blockIdx.x * 8 + (threadIdx.x >> 5);
    int lane = threadIdx.x & 31;
    if (row >= n) return;
    float4 v = *reinterpret_cast<const float4*>(in + (size_t)row * DD + lane * 4);
    v.x = fmaxf(v.x, 0.f); v.y = fmaxf(v.y, 0.f);
    v.z = fmaxf(v.z, 0.f); v.w = fmaxf(v.w, 0.f);
    float s = v.x * v.x + v.y * v.y + v.z * v.z + v.w * v.w;
    #pragma unroll
    for (int o = 16; o; o >>= 1) s += __shfl_xor_sync(0xffffffffu, s, o);
    float sc = 1.f / fmaxf(sqrtf(s), 1e-12f);
    v.x *= sc; v.y *= sc; v.z *= sc; v.w *= sc;
    *reinterpret_cast<float4*>(out + (size_t)row * DD + lane * 4) = v;
}

// Host-side stream/event handles, created ONCE on the first call (the
// correctness run) and reused on every later call, including graph capture.
// This avoids any driver-side allocation during capture. The launched work
// graph is identical on every call, so determinism is unaffected.
struct HostCtx {
    bool init = false;
    cudaStream_t sg[2], ss;
    cudaEvent_t evFork, evPrep0, evPrep1, evG[16], evS[16];
};
static HostCtx hctx;

extern "C" void kernel_launch(void* const* d_in, const int* in_sizes, int n_in,
                              void* d_out, int out_size) {
    const float* ent = (const float*)d_in[0];   // [N, D]
    const float* Tm  = (const float*)d_in[1];   // [R, D, D]
    const float* ev  = (const float*)d_in[2];   // [R, E]
    const int*   er  = (const int*)d_in[3];     // [R, E]
    const int*   ec  = (const int*)d_in[4];     // [R, E]
    float* out = (float*)d_out;

    const int E = in_sizes[2] / RR;

    float *out0, *out1, *Z;
    __nv_bfloat16 *ehi, *elo, *Thi, *Tlo;
    cudaGetSymbolAddress((void**)&out0, g_out0);
    cudaGetSymbolAddress((void**)&out1, g_out1);
    cudaGetSymbolAddress((void**)&Z, g_Z);
    cudaGetSymbolAddress((void**)&ehi, g_ehi);
    cudaGetSymbolAddress((void**)&elo, g_elo);
    cudaGetSymbolAddress((void**)&Thi, g_Thi);
    cudaGetSymbolAddress((void**)&Tlo, g_Tlo);

    if (!hctx.init) {
        cudaFuncSetAttribute(gemm2_kernel, cudaFuncAttributeMaxDynamicSharedMemorySize, SMEM_SZ2);
        cudaStreamCreateWithFlags(&hctx.sg[0], cudaStreamNonBlocking);
        cudaStreamCreateWithFlags(&hctx.sg[1], cudaStreamNonBlocking);
        cudaStreamCreateWithFlags(&hctx.ss, cudaStreamNonBlocking);
        cudaEventCreateWithFlags(&hctx.evFork, cudaEventDisableTiming);
        cudaEventCreateWithFlags(&hctx.evPrep0, cudaEventDisableTiming);
        cudaEventCreateWithFlags(&hctx.evPrep1, cudaEventDisableTiming);
        for (int i = 0; i < 16; i++) {
            cudaEventCreateWithFlags(&hctx.evG[i], cudaEventDisableTiming);
            cudaEventCreateWithFlags(&hctx.evS[i], cudaEventDisableTiming);
        }
        hctx.init = true;
    }
    cudaStream_t* sg = hctx.sg;
    cudaStream_t ss = hctx.ss;

    const int nE = NN * DD;                 // 6.4M
    const int nT = RR * DD * DD;
    const int rowTiles = (NN + 127) / 128;  // 391
    const int sgrid = (2 * E + 7) / 8;
    const size_t ZPAIR = 2 * (size_t)NN * DD;   // one pair-buffer (4 total)

    // Fork
    cudaEventRecord(hctx.evFork, 0);
    cudaStreamWaitEvent(sg[0], hctx.evFork, 0);
    cudaStreamWaitEvent(sg[1], hctx.evFork, 0);
    cudaStreamWaitEvent(ss, hctx.evFork, 0);

    // Prep on main stream: splits + zero(out0). zero(out1) on scatter stream.
    split_kernel<<<(nT / 8 + 255) / 256, 256>>>(Tm, Thi, Tlo, nT / 8, 0);
    split_kernel<<<(nE / 8 + 255) / 256, 256>>>(ent, ehi, elo, nE / 8, 0);
    zero4_kernel<<<(nE / 4 + 255) / 256, 256>>>((float4*)out0, nE / 4);
    cudaEventRecord(hctx.evPrep0, 0);
    cudaStreamWaitEvent(sg[0], hctx.evPrep0, 0);
    cudaStreamWaitEvent(sg[1], hctx.evPrep0, 0);
    cudaStreamWaitEvent(ss, hctx.evPrep0, 0);     // zero(out0) before scatters
    zero4_kernel<<<(nE / 4 + 255) / 256, 256, 0, ss>>>((float4*)out1, nE / 4);

    // ---- layer 1: gemms alternate sg[0]/sg[1] (tail-wave backfill); scatters on ss ----
    for (int p = 0; p < 8; p++) {
        cudaStream_t s = sg[p & 1];
        float* Zb = Z + (p & 3) * ZPAIR;
        if (p >= 4) cudaStreamWaitEvent(s, hctx.evS[p - 4], 0);  // buffer reuse guard
        gemm2_kernel<<<rowTiles, 256, SMEM_SZ2, s>>>(ehi, elo, Thi, Tlo, Zb, 2 * p);
        cudaEventRecord(hctx.evG[p], s);
        cudaStreamWaitEvent(ss, hctx.evG[p], 0);
        scatter_kernel<<<sgrid, 256, 0, ss>>>(Zb, ev, er, ec, out0, E, 2 * p);
        cudaEventRecord(hctx.evS[p], ss);
    }

    // ---- layer 2 split (needs all layer-1 scatters; ss is in-order so evS[7] suffices) ----
    cudaStreamWaitEvent(0, hctx.evS[7], 0);
    split_kernel<<<(nE / 8 + 255) / 256, 256>>>(out0, ehi, elo, nE / 8, 1);
    cudaEventRecord(hctx.evPrep1, 0);
    cudaStreamWaitEvent(sg[0], hctx.evPrep1, 0);
    cudaStreamWaitEvent(sg[1], hctx.evPrep1, 0);

    // ---- layer 2 ----
    for (int p = 0; p < 8; p++) {
        int q = 8 + p;
        cudaStream_t s = sg[p & 1];
        float* Zb = Z + (p & 3) * ZPAIR;
        cudaStreamWaitEvent(s, hctx.evS[q - 4], 0);   // guards vs layer-1 tail scatters too
        gemm2_kernel<<<rowTiles, 256, SMEM_SZ2, s>>>(ehi, elo, Thi, Tlo, Zb, 2 * p);
        cudaEventRecord(hctx.evG[q], s);
        cudaStreamWaitEvent(ss, hctx.evG[q], 0);
        scatter_kernel<<<sgrid, 256, 0, ss>>>(Zb, ev, er, ec, out1, E, 2 * p);
        cudaEventRecord(hctx.evS[q], ss);
    }

    // Join + final normalize.
    cudaStreamWaitEvent(0, hctx.evS[15], 0);
    norm_kernel<<<(NN + 7) / 8, 256>>>(out1, out, NN);
}